// round 3
// baseline (speedup 1.0000x reference)
#include <cuda_runtime.h>
#include <float.h>
#include <stdint.h>

#define B_    2
#define N_    320
#define DIM_  256
#define EDIM_ 128
#define H_    8
#define DH_   64
#define INNER_ 512
#define BN_   (B_*N_)
#define SCALE_ 0.125f  /* 1/sqrt(64) */

// ---------------- scratch (no allocations allowed) ----------------
__device__ float g_q[BN_ * INNER_];        // scaled q
__device__ float g_k[BN_ * INNER_];
__device__ float g_v[BN_ * INNER_];
__device__ float g_t[BN_ * H_ * EDIM_];    // t[b,i,h,c] = We^T q  (scaled)
__device__ int   g_mask[BN_];

// ---------------- mask dtype detection + conversion ----------------
// mask may arrive as uint8 / int32 / float32. Detect from bit patterns of the
// first 128 32-bit words (=512 bytes, strictly in-bounds for every candidate
// layout: u8=640B, i32/f32=2560B).
__global__ void mask_prep_kernel(const unsigned char* __restrict__ mraw) {
    __shared__ int s_f1, s_other;
    if (threadIdx.x == 0) { s_f1 = 0; s_other = 0; }
    __syncthreads();
    const unsigned int* w32 = (const unsigned int*)mraw;
    for (int idx = threadIdx.x; idx < 128; idx += blockDim.x) {
        unsigned int w = w32[idx];
        if (w == 0x3F800000u)        atomicOr(&s_f1, 1);
        else if (w != 0u && w != 1u) atomicOr(&s_other, 1);
    }
    __syncthreads();
    int mode;                 // 0=u8, 1=i32, 2=f32
    if (s_f1)         mode = 2;
    else if (s_other) mode = 0;
    else              mode = 1;
    for (int idx = threadIdx.x; idx < BN_; idx += blockDim.x) {
        int v;
        if (mode == 0)      v = (mraw[idx] != 0);
        else if (mode == 1) v = (((const int*)mraw)[idx] != 0);
        else                v = (((const float*)mraw)[idx] != 0.0f);
        g_mask[idx] = v;
    }
}

// ---------------- q/k/v projection: [640,256] @ [256,1536] ----------------
// cols [0,512)  -> q (bias bq, *SCALE)
// cols [512,1536) -> kv (bias bkv); first 512 -> k, next 512 -> v
__global__ void proj_kernel(const float* __restrict__ nodes,
                            const float* __restrict__ Wq,
                            const float* __restrict__ bq,
                            const float* __restrict__ Wkv,
                            const float* __restrict__ bkv) {
    __shared__ float sA[16][17];
    __shared__ float sB[16][17];
    const int ty = threadIdx.y, tx = threadIdx.x;
    const int row = blockIdx.y * 16 + ty;
    const int col = blockIdx.x * 16 + tx;
    const int col0 = blockIdx.x * 16;
    if (row >= BN_) return;
    float acc = 0.f;
    for (int k0 = 0; k0 < DIM_; k0 += 16) {
        sA[ty][tx] = nodes[row * DIM_ + k0 + tx];
        float bv;
        if (col0 < INNER_) bv = Wq[(k0 + ty) * INNER_ + col];
        else               bv = Wkv[(k0 + ty) * (2 * INNER_) + (col - INNER_)];
        sB[ty][tx] = bv;
        __syncthreads();
#pragma unroll
        for (int kk = 0; kk < 16; kk++) acc += sA[ty][kk] * sB[kk][tx];
        __syncthreads();
    }
    if (col < INNER_) {
        g_q[row * INNER_ + col] = (acc + bq[col]) * SCALE_;
    } else {
        int jj = col - INNER_;
        float o = acc + bkv[jj];
        if (jj < INNER_) g_k[row * INNER_ + jj] = o;
        else             g_v[row * INNER_ + (jj - INNER_)] = o;
    }
}

// ---------------- t projection: t[row,h,c] = sum_d q_s[row,h*64+d]*We[c,h*64+d] ----------------
__global__ void tproj_kernel(const float* __restrict__ We) {
    const int hh = blockIdx.z;
    const int ty = threadIdx.y, tx = threadIdx.x;
    const int c0 = blockIdx.x * 16;
    const int r0 = blockIdx.y * 16;
    __shared__ float sA[16][17];  // [row][d]
    __shared__ float sB[16][17];  // [c][d]
    if (r0 >= BN_) return;
    float acc = 0.f;
    for (int k0 = 0; k0 < DH_; k0 += 16) {
        sA[ty][tx] = g_q[(r0 + ty) * INNER_ + hh * DH_ + k0 + tx];
        sB[ty][tx] = We[(c0 + ty) * INNER_ + hh * DH_ + k0 + tx];
        __syncthreads();
#pragma unroll
        for (int kk = 0; kk < 16; kk++) acc += sA[ty][kk] * sB[tx][kk];
        __syncthreads();
    }
    g_t[(r0 + ty) * (H_ * EDIM_) + hh * EDIM_ + (c0 + tx)] = acc;
}

// ---------------- fused attention main kernel ----------------
// One CTA per (b,i). 8 warps split the j-range (stride 8). Within a warp:
// 4 lanes per head (quad), lane 'sub' owns 16 of 64 k/v dims and 32 of 128
// edge dims. Online softmax per head with deferred rescale. Cross-warp merge
// in smem, then We^T-epilogue on u and the final Wo projection.
__global__ __launch_bounds__(256, 1) void attn_main_kernel(
    const float* __restrict__ edges,
    const float* __restrict__ We,
    const float* __restrict__ be,
    const float* __restrict__ Wo,
    const float* __restrict__ bo,
    float* __restrict__ out) {
    const int bi  = blockIdx.x;
    const int b   = bi / N_;
    const int tid = threadIdx.x;
    const int w    = tid >> 5;
    const int lane = tid & 31;
    const int h    = lane >> 2;
    const int sub  = lane & 3;

    __shared__ float s_part[8][8][128];  // [warp][head][dim] reused for accv then accu
    __shared__ float s_m[8][8];
    __shared__ float s_l[8][8];
    __shared__ float s_wt[8][8];
    __shared__ float s_L[8];
    __shared__ float s_inner[INNER_];
    __shared__ float s_u[H_][EDIM_];

    // per-lane read-only slices of q (scaled) and t (scaled)
    float qr[16], tr[32];
    {
        const float4* qp = (const float4*)(g_q + bi * INNER_ + h * DH_ + sub * 16);
#pragma unroll
        for (int r = 0; r < 4; r++) {
            float4 f = qp[r];
            qr[4*r] = f.x; qr[4*r+1] = f.y; qr[4*r+2] = f.z; qr[4*r+3] = f.w;
        }
        const float4* tp = (const float4*)(g_t + bi * (H_ * EDIM_) + h * EDIM_ + sub * 32);
#pragma unroll
        for (int r = 0; r < 8; r++) {
            float4 f = tp[r];
            tr[4*r] = f.x; tr[4*r+1] = f.y; tr[4*r+2] = f.z; tr[4*r+3] = f.w;
        }
    }

    float accv[16], accu[32];
#pragma unroll
    for (int r = 0; r < 16; r++) accv[r] = 0.f;
#pragma unroll
    for (int r = 0; r < 32; r++) accu[r] = 0.f;
    float m = -FLT_MAX, lsum = 0.f;

    const int    mi    = g_mask[bi];
    const int*   mbase = g_mask + b * N_;
    const float* kbase = g_k + (size_t)b * N_ * INNER_ + h * DH_ + sub * 16;
    const float* vbase = g_v + (size_t)b * N_ * INNER_ + h * DH_ + sub * 16;
    const float* ebase = edges + (size_t)bi * N_ * EDIM_ + sub * 32;

    for (int j = w; j < N_; j += 8) {
        float4 kv[4];
        const float4* kp = (const float4*)(kbase + (size_t)j * INNER_);
#pragma unroll
        for (int r = 0; r < 4; r++) kv[r] = kp[r];
        float4 ev[8];
        const float4* ep = (const float4*)(ebase + (size_t)j * EDIM_);
#pragma unroll
        for (int r = 0; r < 8; r++) ev[r] = ep[r];

        float partial = 0.f;
#pragma unroll
        for (int r = 0; r < 4; r++)
            partial += qr[4*r]*kv[r].x + qr[4*r+1]*kv[r].y + qr[4*r+2]*kv[r].z + qr[4*r+3]*kv[r].w;
#pragma unroll
        for (int r = 0; r < 8; r++)
            partial += tr[4*r]*ev[r].x + tr[4*r+1]*ev[r].y + tr[4*r+2]*ev[r].z + tr[4*r+3]*ev[r].w;
        partial += __shfl_xor_sync(0xffffffffu, partial, 1);
        partial += __shfl_xor_sync(0xffffffffu, partial, 2);

        float simv = (mi && mbase[j]) ? partial : -FLT_MAX;
        float p;
        if (simv > m) {               // quad-uniform branch
            float corr = __expf(m - simv);
            m = simv;
            lsum *= corr;
#pragma unroll
            for (int r = 0; r < 16; r++) accv[r] *= corr;
#pragma unroll
            for (int r = 0; r < 32; r++) accu[r] *= corr;
            p = 1.f;
        } else {
            p = __expf(simv - m);     // masked j after masked start: exp(0)=1 (uniform row, matches jax)
        }
        lsum += p;

        const float4* vp = (const float4*)(vbase + (size_t)j * INNER_);
#pragma unroll
        for (int r = 0; r < 4; r++) {
            float4 f = vp[r];
            accv[4*r]   += p * f.x; accv[4*r+1] += p * f.y;
            accv[4*r+2] += p * f.z; accv[4*r+3] += p * f.w;
        }
#pragma unroll
        for (int r = 0; r < 8; r++) {
            accu[4*r]   += p * ev[r].x; accu[4*r+1] += p * ev[r].y;
            accu[4*r+2] += p * ev[r].z; accu[4*r+3] += p * ev[r].w;
        }
    }

    // ---- merge phase 1: accv + stats ----
#pragma unroll
    for (int r = 0; r < 16; r++) s_part[w][h][sub * 16 + r] = accv[r];
    if (sub == 0) { s_m[w][h] = m; s_l[w][h] = lsum; }
    __syncthreads();

    if (tid < 8) {
        const int hh = tid;
        float M = -FLT_MAX;
#pragma unroll
        for (int ww = 0; ww < 8; ww++) M = fmaxf(M, s_m[ww][hh]);
        float L = 0.f;
#pragma unroll
        for (int ww = 0; ww < 8; ww++) {
            float wt = __expf(s_m[ww][hh] - M);
            s_wt[ww][hh] = wt;
            L += wt * s_l[ww][hh];
        }
        s_L[hh] = L;
    }
    __syncthreads();

    // merged, normalized accv (+be) -> s_inner
    for (int idx = tid; idx < INNER_; idx += 256) {
        const int hh = idx >> 6;
        float v = 0.f;
#pragma unroll
        for (int ww = 0; ww < 8; ww++) v += s_part[ww][hh][idx & 63] * s_wt[ww][hh];
        s_inner[idx] = v / s_L[hh] + be[idx];
    }
    __syncthreads();

    // ---- merge phase 2: accu (reuse s_part) ----
#pragma unroll
    for (int r = 0; r < 32; r++) s_part[w][h][sub * 32 + r] = accu[r];
    __syncthreads();
    for (int idx = tid; idx < H_ * EDIM_; idx += 256) {
        const int hh = idx >> 7, cc = idx & 127;
        float v = 0.f;
#pragma unroll
        for (int ww = 0; ww < 8; ww++) v += s_part[ww][hh][cc] * s_wt[ww][hh];
        s_u[hh][cc] = v / s_L[hh];
    }
    __syncthreads();

    // ---- epilogue: inner += We^T u  (per head) ----
    for (int idx = tid; idx < INNER_; idx += 256) {
        const int hh = idx >> 6;
        float acc = s_inner[idx];
#pragma unroll 4
        for (int c = 0; c < EDIM_; c++) acc += s_u[hh][c] * We[c * INNER_ + idx];
        s_inner[idx] = acc;
    }
    __syncthreads();

    // ---- final projection: out = inner @ Wo + bo ----
    {
        const int o = tid;  // 256 outputs, 256 threads
        float acc = bo[o];
#pragma unroll 8
        for (int in = 0; in < INNER_; in++) acc += s_inner[in] * Wo[in * DIM_ + o];
        out[(size_t)bi * DIM_ + o] = acc;
    }
}

// ---------------- launch ----------------
extern "C" void kernel_launch(void* const* d_in, const int* in_sizes, int n_in,
                              void* d_out, int out_size) {
    const float* nodes = (const float*)d_in[0];
    const float* edges = (const float*)d_in[1];
    const unsigned char* mask = (const unsigned char*)d_in[2];
    const float* Wq  = (const float*)d_in[3];
    const float* bq  = (const float*)d_in[4];
    const float* Wkv = (const float*)d_in[5];
    const float* bkv = (const float*)d_in[6];
    const float* We  = (const float*)d_in[7];
    const float* be  = (const float*)d_in[8];
    const float* Wo  = (const float*)d_in[9];
    const float* bo  = (const float*)d_in[10];
    float* out = (float*)d_out;

    mask_prep_kernel<<<1, 256>>>(mask);
    dim3 tb(16, 16);
    proj_kernel<<<dim3((3 * INNER_) / 16, BN_ / 16), tb>>>(nodes, Wq, bq, Wkv, bkv);
    tproj_kernel<<<dim3(EDIM_ / 16, BN_ / 16, H_), tb>>>(We);
    attn_main_kernel<<<BN_, 256>>>(edges, We, be, Wo, bo, out);
}

// round 5
// speedup vs baseline: 1.2563x; 1.2563x over previous
#include <cuda_runtime.h>
#include <float.h>
#include <stdint.h>

#define B_    2
#define N_    320
#define DIM_  256
#define EDIM_ 128
#define H_    8
#define DH_   64
#define INNER_ 512
#define BN_   (B_*N_)
#define SCALE_ 0.125f  /* 1/sqrt(64) */

// ---------------- scratch (no allocations allowed) ----------------
__device__ float g_q[BN_ * INNER_];        // scaled q
__device__ float g_k[BN_ * INNER_];
__device__ float g_v[BN_ * INNER_];
__device__ float g_t[BN_ * H_ * EDIM_];    // t[b,i,h,c] = We^T q  (scaled)
__device__ int   g_mask[BN_];

// ---------------- mask dtype detection + conversion ----------------
__global__ void mask_prep_kernel(const unsigned char* __restrict__ mraw) {
    __shared__ int s_f1, s_other;
    if (threadIdx.x == 0) { s_f1 = 0; s_other = 0; }
    __syncthreads();
    const unsigned int* w32 = (const unsigned int*)mraw;
    for (int idx = threadIdx.x; idx < 128; idx += blockDim.x) {
        unsigned int w = w32[idx];
        if (w == 0x3F800000u)        atomicOr(&s_f1, 1);
        else if (w != 0u && w != 1u) atomicOr(&s_other, 1);
    }
    __syncthreads();
    int mode;                 // 0=u8, 1=i32, 2=f32
    if (s_f1)         mode = 2;
    else if (s_other) mode = 0;
    else              mode = 1;
    for (int idx = threadIdx.x; idx < BN_; idx += blockDim.x) {
        int v;
        if (mode == 0)      v = (mraw[idx] != 0);
        else if (mode == 1) v = (((const int*)mraw)[idx] != 0);
        else                v = (((const float*)mraw)[idx] != 0.0f);
        g_mask[idx] = v;
    }
}

// ---------------- q/k/v projection ----------------
__global__ void proj_kernel(const float* __restrict__ nodes,
                            const float* __restrict__ Wq,
                            const float* __restrict__ bq,
                            const float* __restrict__ Wkv,
                            const float* __restrict__ bkv) {
    __shared__ float sA[16][17];
    __shared__ float sB[16][17];
    const int ty = threadIdx.y, tx = threadIdx.x;
    const int row = blockIdx.y * 16 + ty;
    const int col = blockIdx.x * 16 + tx;
    const int col0 = blockIdx.x * 16;
    if (row >= BN_) return;
    float acc = 0.f;
    for (int k0 = 0; k0 < DIM_; k0 += 16) {
        sA[ty][tx] = nodes[row * DIM_ + k0 + tx];
        float bv;
        if (col0 < INNER_) bv = Wq[(k0 + ty) * INNER_ + col];
        else               bv = Wkv[(k0 + ty) * (2 * INNER_) + (col - INNER_)];
        sB[ty][tx] = bv;
        __syncthreads();
#pragma unroll
        for (int kk = 0; kk < 16; kk++) acc += sA[ty][kk] * sB[kk][tx];
        __syncthreads();
    }
    if (col < INNER_) {
        g_q[row * INNER_ + col] = (acc + bq[col]) * SCALE_;
    } else {
        int jj = col - INNER_;
        float o = acc + bkv[jj];
        if (jj < INNER_) g_k[row * INNER_ + jj] = o;
        else             g_v[row * INNER_ + (jj - INNER_)] = o;
    }
}

// ---------------- t projection ----------------
__global__ void tproj_kernel(const float* __restrict__ We) {
    const int hh = blockIdx.z;
    const int ty = threadIdx.y, tx = threadIdx.x;
    const int c0 = blockIdx.x * 16;
    const int r0 = blockIdx.y * 16;
    __shared__ float sA[16][17];
    __shared__ float sB[16][17];
    if (r0 >= BN_) return;
    float acc = 0.f;
    for (int k0 = 0; k0 < DH_; k0 += 16) {
        sA[ty][tx] = g_q[(r0 + ty) * INNER_ + hh * DH_ + k0 + tx];
        sB[ty][tx] = We[(c0 + ty) * INNER_ + hh * DH_ + k0 + tx];
        __syncthreads();
#pragma unroll
        for (int kk = 0; kk < 16; kk++) acc += sA[ty][kk] * sB[tx][kk];
        __syncthreads();
    }
    g_t[(r0 + ty) * (H_ * EDIM_) + hh * EDIM_ + (c0 + tx)] = acc;
}

// ---------------- fused attention main kernel ----------------
// One CTA per (b,i). Warp layout: jg = w&3 (4 j-groups, stride 8, 2 j per
// iter), hhalf = w>>2 (heads 0-3 vs 4-7). Within a warp: 8 lanes per head
// (hl = lane>>3, sub = lane&7). Lane owns 8 of 64 k/v dims and 16 of 128
// edge dims. Online softmax per head with paired-j max/rescale.
__global__ __launch_bounds__(256, 2) void attn_main_kernel(
    const float* __restrict__ edges,
    const float* __restrict__ We,
    const float* __restrict__ be,
    const float* __restrict__ Wo,
    const float* __restrict__ bo,
    float* __restrict__ out) {
    const int bi  = blockIdx.x;
    const int b   = bi / N_;
    const int tid = threadIdx.x;
    const int w     = tid >> 5;
    const int lane  = tid & 31;
    const int jg    = w & 3;
    const int hhalf = w >> 2;
    const int hl    = lane >> 3;
    const int sub   = lane & 7;
    const int h     = hhalf * 4 + hl;

    __shared__ float s_part[4][8][128];  // [jgroup][head][dim]; accv then accu
    __shared__ float s_m[4][8];
    __shared__ float s_l[4][8];
    __shared__ float s_wt[4][8];
    __shared__ float s_L[8];
    __shared__ float s_inner[INNER_];
    __shared__ float s_u[H_][EDIM_];

    // per-lane read-only slices
    float qr[8], tr[16];
    {
        const float4* qp = (const float4*)(g_q + bi * INNER_ + h * DH_ + sub * 8);
#pragma unroll
        for (int r = 0; r < 2; r++) {
            float4 f = qp[r];
            qr[4*r] = f.x; qr[4*r+1] = f.y; qr[4*r+2] = f.z; qr[4*r+3] = f.w;
        }
        const float4* tp = (const float4*)(g_t + bi * (H_ * EDIM_) + h * EDIM_ + sub * 16);
#pragma unroll
        for (int r = 0; r < 4; r++) {
            float4 f = tp[r];
            tr[4*r] = f.x; tr[4*r+1] = f.y; tr[4*r+2] = f.z; tr[4*r+3] = f.w;
        }
    }

    float accv[8], accu[16];
#pragma unroll
    for (int r = 0; r < 8; r++)  accv[r] = 0.f;
#pragma unroll
    for (int r = 0; r < 16; r++) accu[r] = 0.f;
    float m = -FLT_MAX, lsum = 0.f;

    const int    mi    = g_mask[bi];
    const int*   mbase = g_mask + b * N_;
    const float* kbase = g_k + (size_t)b * N_ * INNER_ + h * DH_ + sub * 8;
    const float* vbase = g_v + (size_t)b * N_ * INNER_ + h * DH_ + sub * 8;
    const float* ebase = edges + (size_t)bi * N_ * EDIM_ + sub * 16;

#pragma unroll 2
    for (int j0 = jg * 2; j0 < N_; j0 += 8) {
        const int j1 = j0 + 1;
        // ---- loads: k and edges for both j ----
        float4 k0[2], k1[2], e0[4], e1[4];
        {
            const float4* p0 = (const float4*)(kbase + (size_t)j0 * INNER_);
            const float4* p1 = (const float4*)(kbase + (size_t)j1 * INNER_);
            k0[0] = p0[0]; k0[1] = p0[1];
            k1[0] = p1[0]; k1[1] = p1[1];
            const float4* q0 = (const float4*)(ebase + (size_t)j0 * EDIM_);
            const float4* q1 = (const float4*)(ebase + (size_t)j1 * EDIM_);
#pragma unroll
            for (int r = 0; r < 4; r++) { e0[r] = q0[r]; e1[r] = q1[r]; }
        }

        // ---- sim partials (independent chains) ----
        float s0 = 0.f, s1 = 0.f;
#pragma unroll
        for (int r = 0; r < 2; r++) {
            s0 += qr[4*r]*k0[r].x + qr[4*r+1]*k0[r].y + qr[4*r+2]*k0[r].z + qr[4*r+3]*k0[r].w;
            s1 += qr[4*r]*k1[r].x + qr[4*r+1]*k1[r].y + qr[4*r+2]*k1[r].z + qr[4*r+3]*k1[r].w;
        }
#pragma unroll
        for (int r = 0; r < 4; r++) {
            s0 += tr[4*r]*e0[r].x + tr[4*r+1]*e0[r].y + tr[4*r+2]*e0[r].z + tr[4*r+3]*e0[r].w;
            s1 += tr[4*r]*e1[r].x + tr[4*r+1]*e1[r].y + tr[4*r+2]*e1[r].z + tr[4*r+3]*e1[r].w;
        }
        s0 += __shfl_xor_sync(0xffffffffu, s0, 1);
        s1 += __shfl_xor_sync(0xffffffffu, s1, 1);
        s0 += __shfl_xor_sync(0xffffffffu, s0, 2);
        s1 += __shfl_xor_sync(0xffffffffu, s1, 2);
        s0 += __shfl_xor_sync(0xffffffffu, s0, 4);
        s1 += __shfl_xor_sync(0xffffffffu, s1, 4);

        const float s0v = (mi && mbase[j0]) ? s0 : -FLT_MAX;
        const float s1v = (mi && mbase[j1]) ? s1 : -FLT_MAX;

        // ---- paired online softmax update (uniform within 8-lane group) ----
        const float mn = fmaxf(m, fmaxf(s0v, s1v));
        if (mn > m) {
            const float corr = __expf(m - mn);
            m = mn;
            lsum *= corr;
#pragma unroll
            for (int r = 0; r < 8; r++)  accv[r] *= corr;
#pragma unroll
            for (int r = 0; r < 16; r++) accu[r] *= corr;
        }
        const float p0 = __expf(s0v - m);
        const float p1 = __expf(s1v - m);
        lsum += p0 + p1;

        // ---- v loads (k regs dead now) + accumulation ----
        float4 v0[2], v1[2];
        {
            const float4* p0p = (const float4*)(vbase + (size_t)j0 * INNER_);
            const float4* p1p = (const float4*)(vbase + (size_t)j1 * INNER_);
            v0[0] = p0p[0]; v0[1] = p0p[1];
            v1[0] = p1p[0]; v1[1] = p1p[1];
        }
#pragma unroll
        for (int r = 0; r < 2; r++) {
            accv[4*r]   += p0 * v0[r].x + p1 * v1[r].x;
            accv[4*r+1] += p0 * v0[r].y + p1 * v1[r].y;
            accv[4*r+2] += p0 * v0[r].z + p1 * v1[r].z;
            accv[4*r+3] += p0 * v0[r].w + p1 * v1[r].w;
        }
#pragma unroll
        for (int r = 0; r < 4; r++) {
            accu[4*r]   += p0 * e0[r].x + p1 * e1[r].x;
            accu[4*r+1] += p0 * e0[r].y + p1 * e1[r].y;
            accu[4*r+2] += p0 * e0[r].z + p1 * e1[r].z;
            accu[4*r+3] += p0 * e0[r].w + p1 * e1[r].w;
        }
    }

    // ---- merge phase 1: accv + stats ----
#pragma unroll
    for (int r = 0; r < 8; r++) s_part[jg][h][sub * 8 + r] = accv[r];
    if (sub == 0) { s_m[jg][h] = m; s_l[jg][h] = lsum; }
    __syncthreads();

    if (tid < 8) {
        const int hh = tid;
        float M = -FLT_MAX;
#pragma unroll
        for (int g = 0; g < 4; g++) M = fmaxf(M, s_m[g][hh]);
        float L = 0.f;
#pragma unroll
        for (int g = 0; g < 4; g++) {
            float wt = __expf(s_m[g][hh] - M);
            s_wt[g][hh] = wt;
            L += wt * s_l[g][hh];
        }
        s_L[hh] = L;
    }
    __syncthreads();

    // merged, normalized accv (+be) -> s_inner
    for (int idx = tid; idx < INNER_; idx += 256) {
        const int hh = idx >> 6;
        float v = 0.f;
#pragma unroll
        for (int g = 0; g < 4; g++) v += s_part[g][hh][idx & 63] * s_wt[g][hh];
        s_inner[idx] = v / s_L[hh] + be[idx];
    }
    __syncthreads();

    // ---- merge phase 2: accu (reuse s_part) ----
#pragma unroll
    for (int r = 0; r < 16; r++) s_part[jg][h][sub * 16 + r] = accu[r];
    __syncthreads();
    for (int idx = tid; idx < H_ * EDIM_; idx += 256) {
        const int hh = idx >> 7, cc = idx & 127;
        float v = 0.f;
#pragma unroll
        for (int g = 0; g < 4; g++) v += s_part[g][hh][cc] * s_wt[g][hh];
        s_u[hh][cc] = v / s_L[hh];
    }
    __syncthreads();

    // ---- epilogue: inner += We^T u  (per head) ----
    for (int idx = tid; idx < INNER_; idx += 256) {
        const int hh = idx >> 6;
        float acc = s_inner[idx];
#pragma unroll 4
        for (int c = 0; c < EDIM_; c++) acc += s_u[hh][c] * We[c * INNER_ + idx];
        s_inner[idx] = acc;
    }
    __syncthreads();

    // ---- final projection: out = inner @ Wo + bo ----
    {
        const int o = tid;  // 256 outputs, 256 threads
        float acc = bo[o];
#pragma unroll 8
        for (int in = 0; in < INNER_; in++) acc += s_inner[in] * Wo[in * DIM_ + o];
        out[(size_t)bi * DIM_ + o] = acc;
    }
}

// ---------------- launch ----------------
extern "C" void kernel_launch(void* const* d_in, const int* in_sizes, int n_in,
                              void* d_out, int out_size) {
    const float* nodes = (const float*)d_in[0];
    const float* edges = (const float*)d_in[1];
    const unsigned char* mask = (const unsigned char*)d_in[2];
    const float* Wq  = (const float*)d_in[3];
    const float* bq  = (const float*)d_in[4];
    const float* Wkv = (const float*)d_in[5];
    const float* bkv = (const float*)d_in[6];
    const float* We  = (const float*)d_in[7];
    const float* be  = (const float*)d_in[8];
    const float* Wo  = (const float*)d_in[9];
    const float* bo  = (const float*)d_in[10];
    float* out = (float*)d_out;

    mask_prep_kernel<<<1, 256>>>(mask);
    dim3 tb(16, 16);
    proj_kernel<<<dim3((3 * INNER_) / 16, BN_ / 16), tb>>>(nodes, Wq, bq, Wkv, bkv);
    tproj_kernel<<<dim3(EDIM_ / 16, BN_ / 16, H_), tb>>>(We);
    attn_main_kernel<<<BN_, 256>>>(edges, We, be, Wo, bo, out);
}